// round 4
// baseline (speedup 1.0000x reference)
#include <cuda_runtime.h>
#include <math_constants.h>
#include <cstdint>

#define RR 512
#define CC 768
#define DD 256
#define HH 8

#define SCALE_F 0.17677669529663687f   /* 1/sqrt(32) */

#define STAGE_ROWS 32
#define NSTAGE     (RR / STAGE_ROWS)        /* 16 */
#define ROW_STRIDE 1040                      /* 1024 + 16B pad: conflict-free LDS */
#define SLOT_BYTES (STAGE_ROWS * ROW_STRIDE) /* 33280 */

/* smem layout (bytes) */
#define BUF_OFF    0                         /* 2 slots * 33280 = 66560 */
#define P_OFF      66560                     /* 8 * 1040 = 8320        */
#define LOGIT_OFF  74880                     /* 512*9*4 = 18432        */
#define QF_OFF     93312                     /* 256*4   = 1024         */
#define MASK_OFF   94336                     /* 512*4   = 2048         */
#define SMEM_TOTAL 96384                     /* x2 CTA = 188.3 KB/SM   */

__device__ __forceinline__ uint32_t smem_u32(const void* p) {
    uint32_t a;
    asm("{ .reg .u64 t; cvta.to.shared.u64 t, %1; cvt.u32.u64 %0, t; }" : "=r"(a) : "l"(p));
    return a;
}
__device__ __forceinline__ void cp_async16(uint32_t dst, const void* src) {
    uint64_t g;
    asm("cvta.to.global.u64 %0, %1;" : "=l"(g) : "l"(src));
    asm volatile("cp.async.cg.shared.global [%0], [%1], 16;" :: "r"(dst), "l"(g) : "memory");
}
__device__ __forceinline__ void cp_commit() {
    asm volatile("cp.async.commit_group;" ::: "memory");
}
__device__ __forceinline__ void cp_wait1() {
    asm volatile("cp.async.wait_group 1;" ::: "memory");
}
__device__ __forceinline__ void cp_wait0() {
    asm volatile("cp.async.wait_group 0;" ::: "memory");
}
__device__ __forceinline__ unsigned long long fma2(unsigned long long a,
                                                   unsigned long long b,
                                                   unsigned long long c) {
    unsigned long long d;
    asm("fma.rn.f32x2 %0, %1, %2, %3;" : "=l"(d) : "l"(a), "l"(b), "l"(c));
    return d;
}
__device__ __forceinline__ float f2lo(unsigned long long v) {
    return __uint_as_float((unsigned)(v & 0xffffffffull));
}
__device__ __forceinline__ float f2hi(unsigned long long v) {
    return __uint_as_float((unsigned)(v >> 32));
}

// ---------------------------------------------------------------------------
// One fused kernel. Block = one column c.
//  Phase 0: issue cp.async stages 0,1 (msa rows -> smem, padded stride).
//  Phase 1: while those fly, compute p[c][h][:] from Wq/Wk (L2-resident).
//  Phase 2: 16-stage double-buffered main loop, thread=(row,head) full dots,
//           packed f32x2 FMAs, no shuffles.
//  Phase 3: masked softmax over r (warp per head), output [r][c][h].
// ---------------------------------------------------------------------------
__global__ __launch_bounds__(256, 2) void kFused(const float* __restrict__ msa,
                                                 const int* __restrict__ mask,
                                                 const float* __restrict__ Wq,
                                                 const float* __restrict__ Wk,
                                                 float* __restrict__ out) {
    extern __shared__ char sm[];
    const uint32_t smbase = smem_u32(sm);

    const int c    = blockIdx.x;
    const int t    = threadIdx.x;
    const int warp = t >> 5;
    const int lane = t & 31;

    // ---- Phase 0: kick off stages 0 and 1 (all 256 threads issue) ----
#pragma unroll
    for (int s = 0; s < 2; s++) {
#pragma unroll
        for (int i = 0; i < 8; i++) {
            const int k   = t + i * 256;            // 0..2047
            const int row = k >> 6;                 // 0..31
            const int col = k & 63;                 // 16B chunk in row
            uint32_t dst = smbase + BUF_OFF + s * SLOT_BYTES + row * ROW_STRIDE + col * 16;
            const char* src = (const char*)msa
                + ((((size_t)(s * STAGE_ROWS + row)) * CC + c) << 10) + col * 16;
            cp_async16(dst, src);
        }
        cp_commit();
    }

    // ---- mask staging (independent) ----
    ((int*)(sm + MASK_OFF))[t]       = mask[t];
    ((int*)(sm + MASK_OFF))[256 + t] = mask[256 + t];

    // ---- Phase 1a: Qf[j] = SCALE * dot(q[c], Wq[j]); warp-per-row passes ----
    {
        const float4* qrow = (const float4*)(msa + (size_t)c * DD);
        const float4 q4a = qrow[lane];
        const float4 q4b = qrow[32 + lane];
        float* qf = (float*)(sm + QF_OFF);
        for (int jj = 0; jj < 32; jj++) {
            const int j = warp * 32 + jj;
            const float4* wr = (const float4*)(Wq + (size_t)j * DD);
            float4 w0 = wr[lane];
            float4 w1 = wr[32 + lane];
            float v;
            v  = q4a.x * w0.x; v += q4a.y * w0.y; v += q4a.z * w0.z; v += q4a.w * w0.w;
            v += q4b.x * w1.x; v += q4b.y * w1.y; v += q4b.z * w1.z; v += q4b.w * w1.w;
#pragma unroll
            for (int o = 16; o > 0; o >>= 1)
                v += __shfl_xor_sync(0xffffffffu, v, o);
            if (lane == 0) qf[j] = v * SCALE_F;
        }
    }
    __syncthreads();

    // ---- Phase 1b: p[h][:] = sum_{d<32} Qf[h*32+d] * Wk[h*32+d][:]  (warp=h) ----
    {
        const int h  = warp;
        const int dq = lane;
        const float* qf = (const float*)(sm + QF_OFF);
        float4 a0 = make_float4(0.f, 0.f, 0.f, 0.f);
        float4 a1 = make_float4(0.f, 0.f, 0.f, 0.f);
        const float4* wk4 = (const float4*)Wk;
#pragma unroll 8
        for (int d = 0; d < 32; d++) {
            const int rowj = h * 32 + d;
            const float f = qf[rowj];                    // warp-uniform broadcast
            float4 w0 = wk4[(size_t)rowj * 64 + dq];     // coalesced
            float4 w1 = wk4[(size_t)rowj * 64 + 32 + dq];
            a0.x += f * w0.x; a0.y += f * w0.y; a0.z += f * w0.z; a0.w += f * w0.w;
            a1.x += f * w1.x; a1.y += f * w1.y; a1.z += f * w1.z; a1.w += f * w1.w;
        }
        float4* pd = (float4*)(sm + P_OFF + h * ROW_STRIDE);
        pd[dq]      = a0;
        pd[32 + dq] = a1;
    }
    __syncthreads();

    // ---- Phase 2: main loop. thread -> (rloc = t>>3, h = t&7). ----
    const int h    = t & 7;
    const int rloc = t >> 3;
    const char* pbase = sm + P_OFF + h * ROW_STRIDE;
    float* logit = (float*)(sm + LOGIT_OFF);

    for (int s = 0; s < NSTAGE; s++) {
        const int slot = s & 1;
        if (s == NSTAGE - 1) cp_wait0(); else cp_wait1();
        __syncthreads();

        const ulonglong2* r2 = (const ulonglong2*)(sm + BUF_OFF + slot * SLOT_BYTES
                                                   + rloc * ROW_STRIDE);
        const ulonglong2* p2 = (const ulonglong2*)pbase;
        unsigned long long acc0 = 0ull, acc1 = 0ull;
#pragma unroll 8
        for (int i = 0; i < 64; i++) {
            ulonglong2 m  = r2[i];
            ulonglong2 pv = p2[i];
            acc0 = fma2(m.x, pv.x, acc0);
            acc1 = fma2(m.y, pv.y, acc1);
        }
        logit[(s * STAGE_ROWS + rloc) * 9 + h] =
            f2lo(acc0) + f2hi(acc0) + f2lo(acc1) + f2hi(acc1);

        __syncthreads();   // slot fully consumed by all threads

        if (s + 2 < NSTAGE) {
#pragma unroll
            for (int i = 0; i < 8; i++) {
                const int k   = t + i * 256;
                const int row = k >> 6;
                const int col = k & 63;
                uint32_t dst = smbase + BUF_OFF + slot * SLOT_BYTES + row * ROW_STRIDE + col * 16;
                const char* src = (const char*)msa
                    + ((((size_t)((s + 2) * STAGE_ROWS + row)) * CC + c) << 10) + col * 16;
                cp_async16(dst, src);
            }
            cp_commit();
        }
    }
    __syncthreads();

    // ---- Phase 3: masked softmax over r (warp w owns head h = w) ----
    {
        const int hh = warp;
        const int* mask_s = (const int*)(sm + MASK_OFF);
        float vals[16];
        float mx = -CUDART_INF_F;
#pragma unroll
        for (int i = 0; i < 16; i++) {
            const int r = i * 32 + lane;
            float v = logit[r * 9 + hh];
            vals[i] = v;
            if (mask_s[r] != 0) mx = fmaxf(mx, v);
        }
#pragma unroll
        for (int o = 16; o > 0; o >>= 1)
            mx = fmaxf(mx, __shfl_xor_sync(0xffffffffu, mx, o));

        if (mx > -CUDART_INF_F) {
            float sum = 0.f;
#pragma unroll
            for (int i = 0; i < 16; i++) {
                const int r = i * 32 + lane;
                float e = (mask_s[r] != 0) ? __expf(vals[i] - mx) : 0.f;
                vals[i] = e;
                sum += e;
            }
#pragma unroll
            for (int o = 16; o > 0; o >>= 1)
                sum += __shfl_xor_sync(0xffffffffu, sum, o);
            const float inv = 1.f / sum;
#pragma unroll
            for (int i = 0; i < 16; i++) {
                const int r = i * 32 + lane;
                logit[r * 9 + hh] = vals[i] * inv;
            }
        } else {
            // all rows masked -> reference softmaxes equal finfo.min -> uniform
            const float u = 1.0f / (float)RR;
#pragma unroll
            for (int i = 0; i < 16; i++) {
                const int r = i * 32 + lane;
                logit[r * 9 + hh] = u;
            }
        }
    }
    __syncthreads();

    // ---- Output: 8-lane groups write 32B contiguous sectors ----
    {
        const int ho = t & 7;
        const int r0 = t >> 3;
#pragma unroll
        for (int i = 0; i < 16; i++) {
            const int r = i * 32 + r0;
            out[((size_t)r * CC + c) * HH + ho] = logit[r * 9 + ho];
        }
    }
}

// ---------------------------------------------------------------------------
extern "C" void kernel_launch(void* const* d_in, const int* in_sizes, int n_in,
                              void* d_out, int out_size) {
    const float* msa  = (const float*)d_in[0];   // MSA_emb (1,512,768,256) f32
    const int*   mask = (const int*)d_in[1];     // seq_mask (1,512) i32
    const float* Wq   = (const float*)d_in[2];   // (256,256) f32
    const float* Wk   = (const float*)d_in[3];   // (256,256) f32
    float* out = (float*)d_out;                  // (1,512,768,8,1) f32

    cudaFuncSetAttribute(kFused, cudaFuncAttributeMaxDynamicSharedMemorySize,
                         SMEM_TOTAL);
    kFused<<<CC, 256, SMEM_TOTAL>>>(msa, mask, Wq, Wk, out);
}